// round 2
// baseline (speedup 1.0000x reference)
#include <cuda_runtime.h>

#define IMG     512
#define TX      32
#define TY      32
#define KW      11
#define RAD     5
#define HTILE   (TY + KW - 1)   /* 42 */
#define WTILE   (TX + KW - 1)   /* 42 */
#define WPAD    44              /* padded smem row stride */
#define NPLANES 48
#define NBLK    (16 * 16 * 48)  /* 12288 */
#define NPIXD   12582912.0      /* 16*3*512*512 */

// Gaussian window (sigma=1.5, K=11), normalized. Preprocessor literals so the
// fully-unrolled FMA chains fold them into FFMA-imm (rt_SMSP=1 on sm_103a,
// 2x the throughput of 3-reg FFMA) with no LDC traffic.
#define G0  1.0283800e-03f
#define G1  7.5988187e-03f
#define G2  3.6000773e-02f
#define G3  1.0936069e-01f
#define G4  2.1300553e-01f
#define G5  2.6601131e-01f
#define G6  G4
#define G7  G3
#define G8  G2
#define G9  G1
#define G10 G0

// 11-tap convolution of v[i..i+10] as an FMA chain with immediate multipliers.
#define CONV11(v, i)                                                   \
    fmaf(G10, (v)[(i) + 10],                                           \
    fmaf(G9,  (v)[(i) + 9],                                            \
    fmaf(G8,  (v)[(i) + 8],                                            \
    fmaf(G7,  (v)[(i) + 7],                                            \
    fmaf(G6,  (v)[(i) + 6],                                            \
    fmaf(G5,  (v)[(i) + 5],                                            \
    fmaf(G4,  (v)[(i) + 4],                                            \
    fmaf(G3,  (v)[(i) + 3],                                            \
    fmaf(G2,  (v)[(i) + 2],                                            \
    fmaf(G1,  (v)[(i) + 1],                                            \
    G0 * (v)[(i) + 0]))))))))))

__device__ float g_part[NBLK];   // per-block partial sums (deterministic reduction)

// Vertical conv: 4 consecutive output rows for one column of one field.
// col points at H[f][wrow][lane]; stride = TX floats between rows.
__device__ __forceinline__ void vconv4(const float* col, float out[4]) {
    float v[14];
#pragma unroll
    for (int j = 0; j < 14; j++) v[j] = col[j * TX];
#pragma unroll
    for (int i = 0; i < 4; i++) out[i] = CONV11(v, i);
}

__global__ __launch_bounds__(256) void ssim_main(const float* __restrict__ x,
                                                 const float* __restrict__ y) {
    __shared__ float xs[HTILE][WPAD];
    __shared__ float ys[HTILE][WPAD];
    __shared__ float Hs[5][HTILE][TX];   // horizontal conv of {x,y,xx,yy,xy}
    __shared__ float warp_sums[8];

    const int tid   = threadIdx.x;
    const int plane = blockIdx.z;
    const int c0    = blockIdx.x * TX;
    const int r0    = blockIdx.y * TY;
    const float* xp = x + (size_t)plane * (IMG * IMG);
    const float* yp = y + (size_t)plane * (IMG * IMG);

    // ---- Phase 0: cooperative halo load (zero padding at image borders) ----
    for (int i = tid; i < HTILE * WTILE; i += 256) {
        int lr = i / WTILE, lc = i - lr * WTILE;
        int gr = r0 + lr - RAD, gc = c0 + lc - RAD;
        bool ok = (gr >= 0) & (gr < IMG) & (gc >= 0) & (gc < IMG);
        float xv = 0.f, yv = 0.f;
        if (ok) {
            int g = gr * IMG + gc;
            xv = xp[g];
            yv = yp[g];
        }
        xs[lr][lc] = xv;
        ys[lr][lc] = yv;
    }
    __syncthreads();

    // ---- Phase 1: horizontal conv, 4-column register chunks ----
    // 42 rows * 8 chunks = 336 tasks
    for (int t = tid; t < HTILE * (TX / 4); t += 256) {
        int lr  = t >> 3;
        int cc4 = (t & 7) << 2;   // output col base (multiple of 4 -> 16B aligned)

        float xv[16], yv[16];
        *(float4*)(xv + 0)  = *(const float4*)&xs[lr][cc4 + 0];
        *(float4*)(xv + 4)  = *(const float4*)&xs[lr][cc4 + 4];
        *(float4*)(xv + 8)  = *(const float4*)&xs[lr][cc4 + 8];
        *(float4*)(xv + 12) = *(const float4*)&xs[lr][cc4 + 12];
        *(float4*)(yv + 0)  = *(const float4*)&ys[lr][cc4 + 0];
        *(float4*)(yv + 4)  = *(const float4*)&ys[lr][cc4 + 4];
        *(float4*)(yv + 8)  = *(const float4*)&ys[lr][cc4 + 8];
        *(float4*)(yv + 12) = *(const float4*)&ys[lr][cc4 + 12];

        float xx[14], yy[14], xy[14];
#pragma unroll
        for (int i = 0; i < 14; i++) {
            xx[i] = xv[i] * xv[i];
            yy[i] = yv[i] * yv[i];
            xy[i] = xv[i] * yv[i];
        }

        float h0[4], h1[4], h2[4], h3[4], h4[4];
#pragma unroll
        for (int cc = 0; cc < 4; cc++) {
            h0[cc] = CONV11(xv, cc);
            h1[cc] = CONV11(yv, cc);
            h2[cc] = CONV11(xx, cc);
            h3[cc] = CONV11(yy, cc);
            h4[cc] = CONV11(xy, cc);
        }
        // vectorized stores (conflict-free: 16B/lane stride)
        *(float4*)&Hs[0][lr][cc4] = *(float4*)h0;
        *(float4*)&Hs[1][lr][cc4] = *(float4*)h1;
        *(float4*)&Hs[2][lr][cc4] = *(float4*)h2;
        *(float4*)&Hs[3][lr][cc4] = *(float4*)h3;
        *(float4*)&Hs[4][lr][cc4] = *(float4*)h4;
    }
    __syncthreads();

    // ---- Phase 2: vertical conv (4-row window per thread) + SSIM ----
    const int lane = tid & 31;          // output column
    const int wrow = (tid >> 5) << 2;   // output row base: warp w -> rows 4w..4w+3

    float mu1[4], mu2[4], cxx[4], cyy[4], cxy[4];
    vconv4(&Hs[0][wrow][lane], mu1);
    vconv4(&Hs[1][wrow][lane], mu2);
    vconv4(&Hs[2][wrow][lane], cxx);
    vconv4(&Hs[3][wrow][lane], cyy);
    vconv4(&Hs[4][wrow][lane], cxy);

    const float C1 = 0.0001f, C2 = 0.0009f;
    float local = 0.f;
#pragma unroll
    for (int i = 0; i < 4; i++) {
        float m1 = mu1[i], m2 = mu2[i];
        float m1s = m1 * m1, m2s = m2 * m2, m12 = m1 * m2;
        float s1  = cxx[i] - m1s;
        float s2  = cyy[i] - m2s;
        float s12 = cxy[i] - m12;
        float num = (2.f * m12 + C1) * (2.f * s12 + C2);
        float den = (m1s + m2s + C1) * (s1 + s2 + C2);
        local += __fdividef(num, den);
    }

    // ---- block reduction ----
#pragma unroll
    for (int o = 16; o; o >>= 1) local += __shfl_down_sync(0xffffffffu, local, o);
    if (lane == 0) warp_sums[tid >> 5] = local;
    __syncthreads();
    if (tid == 0) {
        float s = 0.f;
#pragma unroll
        for (int w = 0; w < 8; w++) s += warp_sums[w];
        int bidx = (blockIdx.z * 16 + blockIdx.y) * 16 + blockIdx.x;
        g_part[bidx] = s;
    }
}

// Deterministic final reduction (fixed-order tree, no atomics).
__global__ __launch_bounds__(1024) void ssim_fin(float* __restrict__ out) {
    __shared__ double sh[1024];
    int t = threadIdx.x;
    double s = 0.0;
    for (int i = t; i < NBLK; i += 1024) s += (double)g_part[i];
    sh[t] = s;
    __syncthreads();
#pragma unroll
    for (int o = 512; o; o >>= 1) {
        if (t < o) sh[t] += sh[t + o];
        __syncthreads();
    }
    if (t == 0) out[0] = (float)(1.0 - sh[0] / NPIXD);
}

extern "C" void kernel_launch(void* const* d_in, const int* in_sizes, int n_in,
                              void* d_out, int out_size) {
    const float* pred  = (const float*)d_in[0];
    const float* label = (const float*)d_in[1];
    float* out = (float*)d_out;

    dim3 grid(IMG / TX, IMG / TY, NPLANES);   // 16 x 16 x 48
    ssim_main<<<grid, 256>>>(pred, label);
    ssim_fin<<<1, 1024>>>(out);
}